// round 4
// baseline (speedup 1.0000x reference)
#include <cuda_runtime.h>
#include <cuda_bf16.h>
#include <cstdint>

#define NN 50000
#define NE 800000
#define KF 128      // IN_FEAT
#define NH 4        // heads
#define FD 16       // out feat per head
#define HF 64       // NH*FD
#define NEG 0.2f

// Scratch (device globals: allocation-free). float4 typing guarantees 16B alignment.
__device__ float4 g_h[NN * 16];   // h[n][64] as 16 float4 per node
__device__ float4 g_es[NN];       // e_src per node, 4 heads
__device__ float4 g_ed[NN];       // e_dst per node, 4 heads
__device__ int    g_is64;         // 1 if edge_index is int64, else 0 (int32)

// ---------------------------------------------------------------------------
// Kernel 0: probe edge_index dtype. If the int64 interpretation of the first
// 1024 entries is all in [0, NN), it is int64; otherwise int32 pairs.
// Deterministic for fixed inputs.
// ---------------------------------------------------------------------------
__global__ void probe_dtype_kernel(const void* __restrict__ ei_raw)
{
    const long long* e64 = (const long long*)ei_raw;
    const int t = threadIdx.x;            // 256 threads, 4 entries each
    bool ok = true;
    #pragma unroll
    for (int i = 0; i < 4; i++) {
        long long v = e64[t * 4 + i];
        if (v < 0 || v >= NN) ok = false;
    }
    __shared__ int allok;
    if (t == 0) allok = 1;
    __syncthreads();
    if (!ok) atomicAnd(&allok, 0);
    __syncthreads();
    if (t == 0) g_is64 = allok;
}

// ---------------------------------------------------------------------------
// Kernel 1: h = x @ W  (warp per node) fused with per-node attention logits.
// W held in shared as float2 (lane j owns output cols 2j, 2j+1).
// ---------------------------------------------------------------------------
__global__ void __launch_bounds__(256) gemm_logits_kernel(
    const float* __restrict__ x,
    const float* __restrict__ W,
    const float* __restrict__ a)
{
    __shared__ float2 Ws[KF * 32];       // 32 KB
    __shared__ float  xs[8][KF];         // 4 KB (per-warp x row)

    const int tid = threadIdx.x;
    const float2* W2 = reinterpret_cast<const float2*>(W);
    for (int i = tid; i < KF * 32; i += 256) Ws[i] = W2[i];
    __syncthreads();

    const int lane = tid & 31;
    const int w    = tid >> 5;
    const int head = lane >> 3;          // cols 2*lane -> head = lane/8
    const int f0   = (2 * lane) & 15;

    const float as0 = a[head * 32 + f0];
    const float as1 = a[head * 32 + f0 + 1];
    const float ad0 = a[head * 32 + 16 + f0];
    const float ad1 = a[head * 32 + 17 + f0];

    const int nwarps = gridDim.x * 8;
    for (int n = blockIdx.x * 8 + w; n < NN; n += nwarps) {
        // cooperative load of x row (coalesced float4)
        float4 xv = reinterpret_cast<const float4*>(x + (size_t)n * KF)[lane];
        reinterpret_cast<float4*>(xs[w])[lane] = xv;
        __syncwarp();

        float ax = 0.f, ay = 0.f;
        #pragma unroll
        for (int k = 0; k < KF; k++) {
            float  xk = xs[w][k];          // broadcast LDS, conflict-free
            float2 wv = Ws[k * 32 + lane];
            ax = fmaf(xk, wv.x, ax);
            ay = fmaf(xk, wv.y, ay);
        }

        // store h (coalesced float2)
        reinterpret_cast<float2*>(g_h)[(size_t)n * 32 + lane] = make_float2(ax, ay);

        // logits: reduce over the 8 lanes of this head
        float ps = ax * as0 + ay * as1;
        float pd = ax * ad0 + ay * ad1;
        ps += __shfl_xor_sync(0xffffffffu, ps, 1);
        ps += __shfl_xor_sync(0xffffffffu, ps, 2);
        ps += __shfl_xor_sync(0xffffffffu, ps, 4);
        pd += __shfl_xor_sync(0xffffffffu, pd, 1);
        pd += __shfl_xor_sync(0xffffffffu, pd, 2);
        pd += __shfl_xor_sync(0xffffffffu, pd, 4);
        if ((lane & 7) == 0) {
            reinterpret_cast<float*>(g_es)[n * 4 + head] = ps;
            reinterpret_cast<float*>(g_ed)[n * 4 + head] = pd;
        }
        __syncwarp();   // xs reused next iteration
    }
}

// ---------------------------------------------------------------------------
// Kernel 2: per-edge softmax-weighted gather + vectorized scatter-add.
// 16 threads per edge; lane l owns cols [4l, 4l+4) -> head = l/4.
// ---------------------------------------------------------------------------
__device__ __forceinline__ void red_add_v4(float* p, float4 v) {
    asm volatile("red.global.add.v4.f32 [%0], {%1, %2, %3, %4};"
                 :: "l"(p), "f"(v.x), "f"(v.y), "f"(v.z), "f"(v.w)
                 : "memory");
}

__global__ void __launch_bounds__(256) edge_scatter_kernel(
    const void* __restrict__ ei_raw,
    float* __restrict__ out)
{
    const int gtid = blockIdx.x * 256 + threadIdx.x;
    const int e = gtid >> 4;
    if (e >= NE) return;
    const int l = gtid & 15;

    int src, dst;
    if (g_is64) {
        const long long* e64 = (const long long*)ei_raw;
        src = (int)e64[e];
        dst = (int)e64[NE + e];
    } else {
        const int* e32 = (const int*)ei_raw;
        src = e32[e];
        dst = e32[NE + e];
    }

    // per-edge attention (redundant across 16 lanes; tiny L1/L2-resident loads)
    const float4 es = g_es[src];
    const float4 ed = g_ed[dst];
    float z0 = es.x + ed.x; z0 = z0 > 0.f ? z0 : NEG * z0;
    float z1 = es.y + ed.y; z1 = z1 > 0.f ? z1 : NEG * z1;
    float z2 = es.z + ed.z; z2 = z2 > 0.f ? z2 : NEG * z2;
    float z3 = es.w + ed.w; z3 = z3 > 0.f ? z3 : NEG * z3;
    const float m = fmaxf(fmaxf(z0, z1), fmaxf(z2, z3));
    const float p0 = __expf(z0 - m);
    const float p1 = __expf(z1 - m);
    const float p2 = __expf(z2 - m);
    const float p3 = __expf(z3 - m);
    const float inv = 1.0f / (p0 + p1 + p2 + p3);

    const int head = l >> 2;
    const float ph = (head == 0) ? p0 : (head == 1) ? p1 : (head == 2) ? p2 : p3;
    const float alpha = ph * inv;

    // gather h[src] row chunk (coalesced 256B across the 16-lane group)
    const float4 hv = g_h[(size_t)src * 16 + l];
    float4 v = make_float4(alpha * hv.x, alpha * hv.y, alpha * hv.z, alpha * hv.w);

    red_add_v4(out + (size_t)dst * HF + 4 * l, v);
}

// ---------------------------------------------------------------------------
extern "C" void kernel_launch(void* const* d_in, const int* in_sizes, int n_in,
                              void* d_out, int out_size)
{
    const float* x  = (const float*)d_in[0];
    const void*  ei = (const void*)d_in[1];
    const float* W  = (const float*)d_in[2];
    const float* a  = (const float*)d_in[3];
    float* out = (float*)d_out;

    // out accumulates via atomics -> must start zeroed
    cudaMemsetAsync(out, 0, (size_t)out_size * sizeof(float), 0);

    probe_dtype_kernel<<<1, 256>>>(ei);

    gemm_logits_kernel<<<888, 256>>>(x, W, a);

    const int nthreads = NE * 16;
    edge_scatter_kernel<<<(nthreads + 255) / 256, 256>>>(ei, out);

    (void)in_sizes; (void)n_in;
}

// round 6
// speedup vs baseline: 1.3664x; 1.3664x over previous
#include <cuda_runtime.h>
#include <cuda_bf16.h>
#include <cstdint>

#define NN 50000
#define NE 800000
#define KF 128      // IN_FEAT
#define NH 4        // heads
#define FD 16       // out feat per head
#define HF 64       // NH*FD
#define NEG 0.2f

// Scratch (device globals: allocation-free). float4 typing guarantees 16B alignment.
__device__ float4 g_h[NN * 16];   // h[n][64] as 16 float4 per node
__device__ float4 g_es[NN];       // e_src per node, 4 heads
__device__ float4 g_ed[NN];       // e_dst per node, 4 heads
__device__ int    g_is64;         // 1 if edge_index is int64, else 0 (int32)

// ---------------------------------------------------------------------------
// Kernel 1 (fused): out-zeroing + dtype probe + h = x@W + attention logits.
//   - grid-stride zero of out (removes separate memset launch)
//   - block 0 probes edge_index dtype (removes separate probe launch)
//   - GEMM: warp processes 4 nodes at once; each 256B Ws load is amortized
//     over 4 nodes, x broadcasts fetched as float4 once per 4 k-steps.
// ---------------------------------------------------------------------------
__global__ void __launch_bounds__(256) gemm_logits_kernel(
    const float* __restrict__ x,
    const float* __restrict__ W,
    const float* __restrict__ a,
    const void* __restrict__ ei_raw,
    float* __restrict__ out)
{
    const int tid = threadIdx.x;

    // ---- dtype probe (block 0 only; consumed by the NEXT kernel) ----
    if (blockIdx.x == 0) {
        const long long* e64 = (const long long*)ei_raw;
        bool ok = true;
        #pragma unroll
        for (int i = 0; i < 4; i++) {
            long long v = e64[tid * 4 + i];
            if (v < 0 || v >= NN) ok = false;
        }
        __shared__ int allok;
        if (tid == 0) allok = 1;
        __syncthreads();
        if (!ok) atomicAnd(&allok, 0);
        __syncthreads();
        if (tid == 0) g_is64 = allok;
    }

    // ---- zero the output (edge kernel reds into it; runs strictly after) ----
    {
        float4* o4 = reinterpret_cast<float4*>(out);
        const float4 z = make_float4(0.f, 0.f, 0.f, 0.f);
        for (int i = blockIdx.x * 256 + tid; i < NN * 16; i += gridDim.x * 256)
            o4[i] = z;
    }

    // ---- stage W in shared ----
    __shared__ float2 Ws[KF * 32];           // 32 KB; lane j owns cols 2j,2j+1
    __shared__ float4 xs[8][4][KF / 4];      // 16 KB; 4 x-rows per warp

    const float2* W2 = reinterpret_cast<const float2*>(W);
    for (int i = tid; i < KF * 32; i += 256) Ws[i] = W2[i];
    __syncthreads();

    const int lane = tid & 31;
    const int w    = tid >> 5;
    const int head = lane >> 3;              // cols 2*lane -> head = lane/8
    const int f0   = (2 * lane) & 15;

    const float as0 = a[head * 32 + f0];
    const float as1 = a[head * 32 + f0 + 1];
    const float ad0 = a[head * 32 + 16 + f0];
    const float ad1 = a[head * 32 + 17 + f0];

    const int ngroups = NN / 4;              // 12500 exactly
    const int nwarps  = gridDim.x * 8;

    for (int grp = blockIdx.x * 8 + w; grp < ngroups; grp += nwarps) {
        const int n0 = grp * 4;

        // load 4 x rows (each row: 32 float4, one per lane -> fully coalesced)
        #pragma unroll
        for (int j = 0; j < 4; j++)
            xs[w][j][lane] = reinterpret_cast<const float4*>(x + (size_t)(n0 + j) * KF)[lane];
        __syncwarp();

        float ax0 = 0.f, ay0 = 0.f, ax1 = 0.f, ay1 = 0.f;
        float ax2 = 0.f, ay2 = 0.f, ax3 = 0.f, ay3 = 0.f;

        #pragma unroll
        for (int kk = 0; kk < KF / 4; kk++) {
            // one float4 broadcast per node covers 4 k-steps
            const float4 xv0 = xs[w][0][kk];
            const float4 xv1 = xs[w][1][kk];
            const float4 xv2 = xs[w][2][kk];
            const float4 xv3 = xs[w][3][kk];
            const float xk0[4] = {xv0.x, xv0.y, xv0.z, xv0.w};
            const float xk1[4] = {xv1.x, xv1.y, xv1.z, xv1.w};
            const float xk2[4] = {xv2.x, xv2.y, xv2.z, xv2.w};
            const float xk3[4] = {xv3.x, xv3.y, xv3.z, xv3.w};
            #pragma unroll
            for (int dk = 0; dk < 4; dk++) {
                const float2 wv = Ws[(kk * 4 + dk) * 32 + lane];
                ax0 = fmaf(xk0[dk], wv.x, ax0);  ay0 = fmaf(xk0[dk], wv.y, ay0);
                ax1 = fmaf(xk1[dk], wv.x, ax1);  ay1 = fmaf(xk1[dk], wv.y, ay1);
                ax2 = fmaf(xk2[dk], wv.x, ax2);  ay2 = fmaf(xk2[dk], wv.y, ay2);
                ax3 = fmaf(xk3[dk], wv.x, ax3);  ay3 = fmaf(xk3[dk], wv.y, ay3);
            }
        }

        // store h rows (coalesced float2 per node)
        float2* h2 = reinterpret_cast<float2*>(g_h);
        h2[(size_t)(n0 + 0) * 32 + lane] = make_float2(ax0, ay0);
        h2[(size_t)(n0 + 1) * 32 + lane] = make_float2(ax1, ay1);
        h2[(size_t)(n0 + 2) * 32 + lane] = make_float2(ax2, ay2);
        h2[(size_t)(n0 + 3) * 32 + lane] = make_float2(ax3, ay3);

        // logits: reduce over the 8 lanes of each head, for all 4 nodes
        float psv[4], pdv[4];
        psv[0] = ax0 * as0 + ay0 * as1;  pdv[0] = ax0 * ad0 + ay0 * ad1;
        psv[1] = ax1 * as0 + ay1 * as1;  pdv[1] = ax1 * ad0 + ay1 * ad1;
        psv[2] = ax2 * as0 + ay2 * as1;  pdv[2] = ax2 * ad0 + ay2 * ad1;
        psv[3] = ax3 * as0 + ay3 * as1;  pdv[3] = ax3 * ad0 + ay3 * ad1;
        #pragma unroll
        for (int j = 0; j < 4; j++) {
            float ps = psv[j], pd = pdv[j];
            ps += __shfl_xor_sync(0xffffffffu, ps, 1);
            ps += __shfl_xor_sync(0xffffffffu, ps, 2);
            ps += __shfl_xor_sync(0xffffffffu, ps, 4);
            pd += __shfl_xor_sync(0xffffffffu, pd, 1);
            pd += __shfl_xor_sync(0xffffffffu, pd, 2);
            pd += __shfl_xor_sync(0xffffffffu, pd, 4);
            if ((lane & 7) == 0) {
                reinterpret_cast<float*>(g_es)[(n0 + j) * 4 + head] = ps;
                reinterpret_cast<float*>(g_ed)[(n0 + j) * 4 + head] = pd;
            }
        }
        __syncwarp();   // xs reused next iteration
    }
}

// ---------------------------------------------------------------------------
// Kernel 2: per-edge softmax-weighted gather + vectorized scatter-add.
// 16 threads per edge; lane l owns cols [4l, 4l+4) -> head = l/4.
// ---------------------------------------------------------------------------
__device__ __forceinline__ void red_add_v4(float* p, float4 v) {
    asm volatile("red.global.add.v4.f32 [%0], {%1, %2, %3, %4};"
                 :: "l"(p), "f"(v.x), "f"(v.y), "f"(v.z), "f"(v.w)
                 : "memory");
}

__global__ void __launch_bounds__(256) edge_scatter_kernel(
    const void* __restrict__ ei_raw,
    float* __restrict__ out)
{
    const int gtid = blockIdx.x * 256 + threadIdx.x;
    const int e = gtid >> 4;
    if (e >= NE) return;
    const int l = gtid & 15;

    int src, dst;
    if (g_is64) {
        const long long* e64 = (const long long*)ei_raw;
        src = (int)e64[e];
        dst = (int)e64[NE + e];
    } else {
        const int* e32 = (const int*)ei_raw;
        src = e32[e];
        dst = e32[NE + e];
    }

    // per-edge attention (redundant across 16 lanes; L1/L2-resident loads)
    const float4 es = g_es[src];
    const float4 ed = g_ed[dst];
    float z0 = es.x + ed.x; z0 = z0 > 0.f ? z0 : NEG * z0;
    float z1 = es.y + ed.y; z1 = z1 > 0.f ? z1 : NEG * z1;
    float z2 = es.z + ed.z; z2 = z2 > 0.f ? z2 : NEG * z2;
    float z3 = es.w + ed.w; z3 = z3 > 0.f ? z3 : NEG * z3;
    const float m = fmaxf(fmaxf(z0, z1), fmaxf(z2, z3));
    const float p0 = __expf(z0 - m);
    const float p1 = __expf(z1 - m);
    const float p2 = __expf(z2 - m);
    const float p3 = __expf(z3 - m);
    const float inv = 1.0f / (p0 + p1 + p2 + p3);

    const int head = l >> 2;
    const float ph = (head == 0) ? p0 : (head == 1) ? p1 : (head == 2) ? p2 : p3;
    const float alpha = ph * inv;

    // gather h[src] row chunk (coalesced 256B across the 16-lane group)
    const float4 hv = g_h[(size_t)src * 16 + l];
    float4 v = make_float4(alpha * hv.x, alpha * hv.y, alpha * hv.z, alpha * hv.w);

    red_add_v4(out + (size_t)dst * HF + 4 * l, v);
}

// ---------------------------------------------------------------------------
extern "C" void kernel_launch(void* const* d_in, const int* in_sizes, int n_in,
                              void* d_out, int out_size)
{
    const float* x  = (const float*)d_in[0];
    const void*  ei = (const void*)d_in[1];
    const float* W  = (const float*)d_in[2];
    const float* a  = (const float*)d_in[3];
    float* out = (float*)d_out;

    // Kernel 1 zeroes out, probes dtype, computes h + logits.
    gemm_logits_kernel<<<592, 256>>>(x, W, a, ei, out);

    // Kernel 2 consumes h/logits/flag, reds into out.
    const int nthreads = NE * 16;
    edge_scatter_kernel<<<(nthreads + 255) / 256, 256>>>(ei, out);

    (void)in_sizes; (void)n_in; (void)out_size;
}